// round 3
// baseline (speedup 1.0000x reference)
#include <cuda_runtime.h>
#include <cuda_fp16.h>
#include <cstdint>

// TangentLin: complex linear out = x @ (Re + i Im)^T as ONE real GEMM
//   A = [x_re | x_im]            (M x 1024)  fp32 -> fp16 on the fly
//   Bt[j,k] (1024 x 1024 fp16):  j<512: [Re | -Im],  j>=512: [Im | Re]
//   out[n, j] = sum_k A[n,k] * Bt[j,k];  j<512 -> out_re, j>=512 -> out_im

#define M_TOTAL 100000
#define CH 512
#define GK 1024
#define GN 1024
#define BM 128
#define BN 128
#define BK 32
#define NTHREADS 256
#define PAD 40   // halves per smem row (80B: 16B-aligned, conflict-free ldmatrix)

__device__ __half g_Bt[GN * GK];  // 2 MB scratch (sanctioned __device__ global)

__global__ void build_Bt_kernel(const float* __restrict__ Re,
                                const float* __restrict__ Im) {
    int idx = blockIdx.x * blockDim.x + threadIdx.x;
    if (idx >= GN * GK) return;
    int j = idx >> 10;
    int k = idx & 1023;
    float v;
    if (j < CH) {
        v = (k < CH) ? Re[j * CH + k] : -Im[j * CH + (k - CH)];
    } else {
        v = (k < CH) ? Im[(j - CH) * CH + k] : Re[(j - CH) * CH + (k - CH)];
    }
    g_Bt[idx] = __float2half_rn(v);
}

__device__ __forceinline__ uint32_t smem_u32(const void* p) {
    return (uint32_t)__cvta_generic_to_shared(p);
}

__device__ __forceinline__ void ldsm_x4(uint32_t& r0, uint32_t& r1,
                                        uint32_t& r2, uint32_t& r3,
                                        uint32_t addr) {
    asm volatile("ldmatrix.sync.aligned.m8n8.x4.shared.b16 {%0,%1,%2,%3}, [%4];\n"
                 : "=r"(r0), "=r"(r1), "=r"(r2), "=r"(r3)
                 : "r"(addr));
}

__device__ __forceinline__ void mma16816(float* c,
                                         uint32_t a0, uint32_t a1, uint32_t a2, uint32_t a3,
                                         uint32_t b0, uint32_t b1) {
    asm volatile("mma.sync.aligned.m16n8k16.row.col.f32.f16.f16.f32 "
                 "{%0,%1,%2,%3}, {%4,%5,%6,%7}, {%8,%9}, {%0,%1,%2,%3};\n"
                 : "+f"(c[0]), "+f"(c[1]), "+f"(c[2]), "+f"(c[3])
                 : "r"(a0), "r"(a1), "r"(a2), "r"(a3), "r"(b0), "r"(b1));
}

__global__ __launch_bounds__(NTHREADS)
void cgemm_kernel(const float* __restrict__ x_re,
                  const float* __restrict__ x_im,
                  float* __restrict__ out) {
    __shared__ __half As[2][BM * PAD];
    __shared__ __half Bs[2][BN * PAD];

    const int tid  = threadIdx.x;
    const int lane = tid & 31;
    const int warp = tid >> 5;
    const int wm   = warp >> 2;   // 0..1  (64 rows of M each)
    const int wn   = warp & 3;    // 0..3  (32 cols of N each)
    const int bm   = blockIdx.y;
    const int bn   = blockIdx.x;

    // global-load indexing
    const int a_r0 = tid >> 3;    // + i*32 ; 8 float4 per 32-float row
    const int a_c  = tid & 7;
    const int b_r0 = tid >> 2;    // + i*64 ; 4 uint4 per 32-half row
    const int b_c  = tid & 3;

    float4 aReg[4];
    uint4  bReg[2];

    float acc[4][4][4];
    #pragma unroll
    for (int mi = 0; mi < 4; ++mi)
        #pragma unroll
        for (int ni = 0; ni < 4; ++ni)
            #pragma unroll
            for (int r = 0; r < 4; ++r) acc[mi][ni][r] = 0.f;

    // smem-read (ldmatrix) indexing
    const int a_row_in = wm * 64 + (lane & 15);
    const int b_row_in = wn * 32 + (lane & 15);
    const int koff     = (lane >> 4) * 8;

    auto fetch = [&](int kt) {
        const int k0 = kt * BK;
        const float* xs = (k0 < CH) ? x_re : x_im;
        const int colA = (k0 & (CH - 1)) + a_c * 4;
        #pragma unroll
        for (int i = 0; i < 4; ++i) {
            int row_g = bm * BM + a_r0 + i * 32;
            if (row_g < M_TOTAL)
                aReg[i] = *(const float4*)(xs + (size_t)row_g * CH + colA);
            else
                aReg[i] = make_float4(0.f, 0.f, 0.f, 0.f);
        }
        #pragma unroll
        for (int i = 0; i < 2; ++i) {
            int n_g = bn * BN + b_r0 + i * 64;
            bReg[i] = *(const uint4*)(g_Bt + (size_t)n_g * GK + k0 + b_c * 8);
        }
    };

    auto stsAB = [&](int s) {
        #pragma unroll
        for (int i = 0; i < 4; ++i) {
            __half2 h0 = __floats2half2_rn(aReg[i].x, aReg[i].y);
            __half2 h1 = __floats2half2_rn(aReg[i].z, aReg[i].w);
            uint2 v;
            v.x = *(uint32_t*)&h0;
            v.y = *(uint32_t*)&h1;
            *(uint2*)&As[s][(a_r0 + i * 32) * PAD + a_c * 4] = v;
        }
        #pragma unroll
        for (int i = 0; i < 2; ++i) {
            *(uint4*)&Bs[s][(b_r0 + i * 64) * PAD + b_c * 8] = bReg[i];
        }
    };

    fetch(0);
    stsAB(0);
    __syncthreads();

    const int KT = GK / BK;  // 32
    for (int kt = 0; kt < KT; ++kt) {
        const int s = kt & 1;
        if (kt < KT - 1) fetch(kt + 1);

        #pragma unroll
        for (int ks = 0; ks < 2; ++ks) {
            uint32_t a[4][4];
            #pragma unroll
            for (int mi = 0; mi < 4; ++mi) {
                uint32_t addr = smem_u32(&As[s][(a_row_in + mi * 16) * PAD + koff + ks * 16]);
                ldsm_x4(a[mi][0], a[mi][1], a[mi][2], a[mi][3], addr);
            }
            uint32_t b[4][2];
            #pragma unroll
            for (int pair = 0; pair < 2; ++pair) {
                uint32_t r0, r1, r2, r3;
                uint32_t addr = smem_u32(&Bs[s][(b_row_in + pair * 16) * PAD + koff + ks * 16]);
                ldsm_x4(r0, r1, r2, r3, addr);
                b[pair * 2][0]     = r0;
                b[pair * 2][1]     = r2;
                b[pair * 2 + 1][0] = r1;
                b[pair * 2 + 1][1] = r3;
            }
            #pragma unroll
            for (int mi = 0; mi < 4; ++mi)
                #pragma unroll
                for (int ni = 0; ni < 4; ++ni)
                    mma16816(acc[mi][ni],
                             a[mi][0], a[mi][1], a[mi][2], a[mi][3],
                             b[ni][0], b[ni][1]);
        }

        if (kt < KT - 1) {
            stsAB(s ^ 1);
            __syncthreads();
        }
    }

    // epilogue: j<512 -> out_re plane, j>=512 -> out_im plane
    const int jhalf = bn >> 2;
    float* outb = out + (size_t)jhalf * M_TOTAL * CH;
    #pragma unroll
    for (int mi = 0; mi < 4; ++mi) {
        int r = bm * BM + wm * 64 + mi * 16 + (lane >> 2);
        #pragma unroll
        for (int ni = 0; ni < 4; ++ni) {
            int c = (bn & 3) * BN + wn * 32 + ni * 8 + (lane & 3) * 2;
            if (r < M_TOTAL) {
                float2 v = make_float2(acc[mi][ni][0], acc[mi][ni][1]);
                *(float2*)(outb + (size_t)r * CH + c) = v;
            }
            if (r + 8 < M_TOTAL) {
                float2 v = make_float2(acc[mi][ni][2], acc[mi][ni][3]);
                *(float2*)(outb + (size_t)(r + 8) * CH + c) = v;
            }
        }
    }
}

extern "C" void kernel_launch(void* const* d_in, const int* in_sizes, int n_in,
                              void* d_out, int out_size) {
    const float* x_re = (const float*)d_in[0];
    const float* x_im = (const float*)d_in[1];
    const float* Re   = (const float*)d_in[2];
    const float* Im   = (const float*)d_in[3];
    float* out = (float*)d_out;
    (void)in_sizes; (void)n_in; (void)out_size;

    build_Bt_kernel<<<(GN * GK + 255) / 256, 256>>>(Re, Im);

    dim3 grid(GN / BN, (M_TOTAL + BM - 1) / BM);
    cgemm_kernel<<<grid, NTHREADS>>>(x_re, x_im, out);
}

// round 5
// speedup vs baseline: 1.1755x; 1.1755x over previous
#include <cuda_runtime.h>
#include <cuda_fp16.h>
#include <cstdint>

// TangentLin as ONE fused real GEMM on mma.sync (HMMA), zero-smem design:
//   A = [x_re | x_im]            (M x 1024) fp32 -> fp16 fragment scratch
//   Bt[j,k] (1024 x 1024 fp16):  j<512: [Re | -Im],  j>=512: [Im | Re]
//   Both operands pre-packed in mma.m16n8k16 fragment-linear layout so the
//   GEMM inner loop is pure LDG.128 + HMMA (no STS / ldmatrix / syncthreads).

#define M_TOTAL 100000
#define CH      512
#define GK      1024
#define GN      1024
#define MPAD    100096          // 782 * 128
#define MT      (MPAD / 16)     // 6256 m16-tiles
#define KT16    (GK / 16)       // 64
#define KT32    (GK / 32)       // 32
#define NT8     (GN / 8)        // 128 n8-tiles
#define NTHREADS 256

// A fragments: [(mt * KT16 + kt16) * 32 + lane] -> uint4 {a0,a1,a2,a3}
//   a0 = A[mt*16 + l/4      ][kt*16 + 2*(l%4) + {0,1}]
//   a1 = A[mt*16 + l/4 + 8  ][same k]
//   a2 = A[row              ][k + 8]
//   a3 = A[row + 8          ][k + 8]
__device__ uint4 g_Af[MT * KT16 * 32];            // 205 MB scratch

// B fragments: [(nt * KT32 + g) * 32 + lane] -> uint4 {b0a,b1a,b0b,b1b}
//   n  = nt*8 + l/4, ka = g*32 + 2*(l%4)
//   b0a = Bt[n][ka,ka+1]  b1a = Bt[n][ka+8,ka+9]
//   b0b = Bt[n][ka+16,..] b1b = Bt[n][ka+24,..]
__device__ uint4 g_Bf[NT8 * KT32 * 32];           // 2 MB scratch

__global__ void prep_A(const float* __restrict__ x_re,
                       const float* __restrict__ x_im) {
    int idx = blockIdx.x * blockDim.x + threadIdx.x;
    if (idx >= MT * KT16 * 32) return;
    const int lane = idx & 31;
    const int kt   = (idx >> 5) & (KT16 - 1);
    const int mt   = idx >> 11;

    const int row = mt * 16 + (lane >> 2);
    const int k0  = kt * 16 + 2 * (lane & 3);
    const float* xs = (k0 < CH) ? x_re : x_im;
    const int kk = k0 & (CH - 1);        // 16-chunks never straddle the 512 split

    float2 z = make_float2(0.f, 0.f);
    float2 p0 = z, p1 = z, p2 = z, p3 = z;
    if (row < M_TOTAL) {
        const float* p = xs + (size_t)row * CH + kk;
        p0 = *(const float2*)p;
        p2 = *(const float2*)(p + 8);
    }
    if (row + 8 < M_TOTAL) {
        const float* p = xs + (size_t)(row + 8) * CH + kk;
        p1 = *(const float2*)p;
        p3 = *(const float2*)(p + 8);
    }
    uint4 v;
    __half2 h;
    h = __floats2half2_rn(p0.x, p0.y); v.x = *(uint32_t*)&h;
    h = __floats2half2_rn(p1.x, p1.y); v.y = *(uint32_t*)&h;
    h = __floats2half2_rn(p2.x, p2.y); v.z = *(uint32_t*)&h;
    h = __floats2half2_rn(p3.x, p3.y); v.w = *(uint32_t*)&h;
    g_Af[idx] = v;
}

__device__ __forceinline__ uint32_t bt_pair(const float* __restrict__ Re,
                                            const float* __restrict__ Im,
                                            int j, int k) {
    const float* src;
    float sgn = 1.f;
    if (j < CH) {
        if (k < CH) src = Re + (size_t)j * CH + k;
        else { src = Im + (size_t)j * CH + (k - CH); sgn = -1.f; }
    } else {
        if (k < CH) src = Im + (size_t)(j - CH) * CH + k;
        else        src = Re + (size_t)(j - CH) * CH + (k - CH);
    }
    float2 v = *(const float2*)src;
    __half2 h = __floats2half2_rn(sgn * v.x, sgn * v.y);
    return *(uint32_t*)&h;
}

__global__ void prep_B(const float* __restrict__ Re,
                       const float* __restrict__ Im) {
    int idx = blockIdx.x * blockDim.x + threadIdx.x;
    if (idx >= NT8 * KT32 * 32) return;
    const int lane = idx & 31;
    const int g    = (idx >> 5) & (KT32 - 1);
    const int nt   = idx >> 10;

    const int n  = nt * 8 + (lane >> 2);
    const int ka = g * 32 + 2 * (lane & 3);  // 32-chunks never straddle 512

    uint4 v;
    v.x = bt_pair(Re, Im, n, ka);
    v.y = bt_pair(Re, Im, n, ka + 8);
    v.z = bt_pair(Re, Im, n, ka + 16);
    v.w = bt_pair(Re, Im, n, ka + 24);
    g_Bf[idx] = v;
}

__device__ __forceinline__ void mma16816(float* c,
                                         uint32_t a0, uint32_t a1, uint32_t a2, uint32_t a3,
                                         uint32_t b0, uint32_t b1) {
    asm volatile("mma.sync.aligned.m16n8k16.row.col.f32.f16.f16.f32 "
                 "{%0,%1,%2,%3}, {%4,%5,%6,%7}, {%8,%9}, {%0,%1,%2,%3};\n"
                 : "+f"(c[0]), "+f"(c[1]), "+f"(c[2]), "+f"(c[3])
                 : "r"(a0), "r"(a1), "r"(a2), "r"(a3), "r"(b0), "r"(b1));
}

__global__ __launch_bounds__(NTHREADS, 2)
void gemm_frag(float* __restrict__ out) {
    const int tid  = threadIdx.x;
    const int lane = tid & 31;
    const int warp = tid >> 5;
    const int wm   = warp >> 2;        // 0..1 : 64 rows each
    const int wn   = warp & 3;         // 0..3 : 32 cols each
    const int bn   = blockIdx.x;       // 0..7  (fastest -> A-frag L2 reuse)
    const int bm   = blockIdx.y;       // 0..781

    float acc[4][4][4];
    #pragma unroll
    for (int mi = 0; mi < 4; ++mi)
        #pragma unroll
        for (int ni = 0; ni < 4; ++ni)
            #pragma unroll
            for (int r = 0; r < 4; ++r) acc[mi][ni][r] = 0.f;

    const int mtb = bm * 8 + wm * 4;   // first m16-tile of this warp
    const int ntb = bn * 16 + wn * 4;  // first n8-tile of this warp

    for (int g = 0; g < KT32; ++g) {
        uint4 bf[4], a0[4], a1[4];
        #pragma unroll
        for (int ni = 0; ni < 4; ++ni)
            bf[ni] = g_Bf[(((ntb + ni) * KT32 + g) << 5) + lane];
        #pragma unroll
        for (int mi = 0; mi < 4; ++mi)
            a0[mi] = g_Af[(((mtb + mi) * KT16 + 2 * g) << 5) + lane];
        #pragma unroll
        for (int mi = 0; mi < 4; ++mi)
            a1[mi] = g_Af[(((mtb + mi) * KT16 + 2 * g + 1) << 5) + lane];

        #pragma unroll
        for (int mi = 0; mi < 4; ++mi)
            #pragma unroll
            for (int ni = 0; ni < 4; ++ni)
                mma16816(acc[mi][ni],
                         a0[mi].x, a0[mi].y, a0[mi].z, a0[mi].w,
                         bf[ni].x, bf[ni].y);
        #pragma unroll
        for (int mi = 0; mi < 4; ++mi)
            #pragma unroll
            for (int ni = 0; ni < 4; ++ni)
                mma16816(acc[mi][ni],
                         a1[mi].x, a1[mi].y, a1[mi].z, a1[mi].w,
                         bf[ni].z, bf[ni].w);
    }

    // epilogue: j<512 -> re-plane, j>=512 -> im-plane (validated in round 0)
    const int jhalf = bn >> 2;
    float* outb = out + (size_t)jhalf * M_TOTAL * CH;
    #pragma unroll
    for (int mi = 0; mi < 4; ++mi) {
        int r = bm * 128 + wm * 64 + mi * 16 + (lane >> 2);
        #pragma unroll
        for (int ni = 0; ni < 4; ++ni) {
            int c = (bn & 3) * 128 + wn * 32 + ni * 8 + (lane & 3) * 2;
            if (r < M_TOTAL) {
                float2 v = make_float2(acc[mi][ni][0], acc[mi][ni][1]);
                *(float2*)(outb + (size_t)r * CH + c) = v;
            }
            if (r + 8 < M_TOTAL) {
                float2 v = make_float2(acc[mi][ni][2], acc[mi][ni][3]);
                *(float2*)(outb + (size_t)(r + 8) * CH + c) = v;
            }
        }
    }
}

extern "C" void kernel_launch(void* const* d_in, const int* in_sizes, int n_in,
                              void* d_out, int out_size) {
    const float* x_re = (const float*)d_in[0];
    const float* x_im = (const float*)d_in[1];
    const float* Re   = (const float*)d_in[2];
    const float* Im   = (const float*)d_in[3];
    float* out = (float*)d_out;
    (void)in_sizes; (void)n_in; (void)out_size;

    prep_A<<<(MT * KT16 * 32 + 255) / 256, 256>>>(x_re, x_im);
    prep_B<<<(NT8 * KT32 * 32 + 255) / 256, 256>>>(Re, Im);

    dim3 grid(GN / 128, MPAD / 128);   // (8, 782), bn fastest
    gemm_frag<<<grid, NTHREADS>>>(out);
}